// round 16
// baseline (speedup 1.0000x reference)
#include <cuda_runtime.h>
#include <cuda_bf16.h>
#include <cstdint>

#define NN   50000
#define EE   800000
#define INF  128
#define HH   256
#define H3   768

// ---------------- scratch (static device globals; no allocations) ----------
__device__ float    g_h    [(size_t)NN * HH];          // pre-BN hidden (fp32)
__device__ uint32_t g_aggH [(size_t)NN * 128];         // split (x+agg) packed k-pairs
__device__ uint32_t g_aggL [(size_t)NN * 128];
__device__ uint32_t g_catH [(size_t)NN * 384];         // split concat(h1,h2,h3)
__device__ uint32_t g_catL [(size_t)NN * 384];
__device__ uint32_t g_WH   [475136];                   // split weights [K/2][N]
__device__ uint32_t g_WL   [475136];
__device__ float    g_sum  [HH];                       // zero at load; reset by agg/init
__device__ float    g_sumsq[HH];
__device__ int      g_deg  [NN];                       // zero at load; scan_k re-zeroes
__device__ int      g_off  [NN + 1];
__device__ int      g_cur  [NN];
__device__ int      g_col  [EE];

#define W_C1W1 0
#define W_C1W2 16384
#define W_C2W1 49152
#define W_C2W2 81920
#define W_C3W1 114688
#define W_C3W2 147456
#define W_LIN1 180224
#define W_TOT  475136

// ---------------- bf16 split helpers ----------------------------------------
__device__ __forceinline__ uint32_t pk2(__nv_bfloat16 lo, __nv_bfloat16 hi)
{
    __nv_bfloat162 t; t.x = lo; t.y = hi;
    return *reinterpret_cast<uint32_t*>(&t);
}
__device__ __forceinline__ void bfsplit2(float v0, float v1,
                                         uint32_t& hw, uint32_t& lw)
{
    __nv_bfloat16 h0 = __float2bfloat16(v0);
    __nv_bfloat16 h1 = __float2bfloat16(v1);
    float l0 = v0 - __bfloat162float(h0);
    float l1 = v1 - __bfloat162float(h1);
    hw = pk2(h0, h1);
    lw = pk2(__float2bfloat16(l0), __float2bfloat16(l1));
}
__device__ __forceinline__ float2 up2(uint32_t w)
{
    __nv_bfloat162 t = *reinterpret_cast<__nv_bfloat162*>(&w);
    return make_float2(__bfloat162float(t.x), __bfloat162float(t.y));
}

// ---------------- cp.async helpers -------------------------------------------
#define CP16(dst, src) \
    asm volatile("cp.async.ca.shared.global [%0], [%1], 16;" :: "r"(dst), "l"(src) : "memory")
#define CP_COMMIT() asm volatile("cp.async.commit_group;" ::: "memory")
#define CP_WAIT0()  asm volatile("cp.async.wait_group 0;"  ::: "memory")

__device__ __forceinline__ uint32_t s2u(const void* p)
{
    return (uint32_t)__cvta_generic_to_shared(p);
}

// ================= consolidated weight pre-split =============================
__global__ void prep_all(const float* __restrict__ w0, const float* __restrict__ w1,
                         const float* __restrict__ w2, const float* __restrict__ w3,
                         const float* __restrict__ w4, const float* __restrict__ w5,
                         const float* __restrict__ w6,
                         uint32_t* __restrict__ H, uint32_t* __restrict__ L)
{
    int idx = blockIdx.x * blockDim.x + threadIdx.x;
    if (idx >= W_TOT) return;
    const float* src;
    int base, n;
    if      (idx < W_C1W2) { src = w0; base = W_C1W1; n = HH; }
    else if (idx < W_C2W1) { src = w1; base = W_C1W2; n = HH; }
    else if (idx < W_C2W2) { src = w2; base = W_C2W1; n = HH; }
    else if (idx < W_C3W1) { src = w3; base = W_C2W2; n = HH; }
    else if (idx < W_C3W2) { src = w4; base = W_C3W1; n = HH; }
    else if (idx < W_LIN1) { src = w5; base = W_C3W2; n = HH; }
    else                   { src = w6; base = W_LIN1; n = H3; }
    int loc = idx - base;
    int k2 = loc / n, nn = loc - k2 * n;
    float v0 = src[(size_t)(2 * k2)     * n + nn];
    float v1 = src[(size_t)(2 * k2 + 1) * n + nn];
    bfsplit2(v0, v1, H[idx], L[idx]);
}

// ================= CSR build =================================================
__global__ void hist_k(const int* __restrict__ ei, int* __restrict__ deg)
{
    int e = blockIdx.x * blockDim.x + threadIdx.x;
    if (e < EE) atomicAdd(&deg[ei[EE + e]], 1);
}

// scan + self-reset of deg (keeps launch-invariant: deg == 0 on entry)
__global__ void scan_k(int* __restrict__ deg, int* __restrict__ off,
                       int* __restrict__ cur)
{
    __shared__ int wsum[32];
    __shared__ int carry;
    int tid = threadIdx.x, lane = tid & 31, w = tid >> 5;
    if (tid == 0) { carry = 0; off[0] = 0; }
    __syncthreads();
    for (int base = 0; base < NN; base += 1024) {
        int i = base + tid;
        int v = 0;
        if (i < NN) { v = deg[i]; deg[i] = 0; }
        int s = v;
#pragma unroll
        for (int o = 1; o < 32; o <<= 1) {
            int t = __shfl_up_sync(0xffffffffu, s, o);
            if (lane >= o) s += t;
        }
        if (lane == 31) wsum[w] = s;
        __syncthreads();
        if (w == 0) {
            int ws = wsum[lane];
#pragma unroll
            for (int o = 1; o < 32; o <<= 1) {
                int t = __shfl_up_sync(0xffffffffu, ws, o);
                if (lane >= o) ws += t;
            }
            wsum[lane] = ws;
        }
        __syncthreads();
        int inc = s + (w > 0 ? wsum[w - 1] : 0) + carry;
        if (i < NN) { off[i + 1] = inc; cur[i] = inc - v; }
        int tot = wsum[31];
        __syncthreads();
        if (tid == 0) carry += tot;
        __syncthreads();
    }
}

__global__ void fill_k(const int* __restrict__ ei, int* __restrict__ cur,
                       int* __restrict__ col)
{
    int e = blockIdx.x * blockDim.x + threadIdx.x;
    if (e < EE) {
        int p = atomicAdd(&cur[ei[EE + e]], 1);
        col[p] = ei[e];
    }
}

// ===== layer-1 aggregation from fp32 x: split(x + sum_neighbors x) ==========
// 4-neighbor unrolled (4 independent float4 streams in flight).
__global__ __launch_bounds__(256)
void csr_agg1(const float* __restrict__ x,
              const int* __restrict__ off, const int* __restrict__ col,
              uint32_t* __restrict__ aggH, uint32_t* __restrict__ aggL)
{
    int warp = (blockIdx.x * blockDim.x + threadIdx.x) >> 5;
    int lane = threadIdx.x & 31;
    if (warp >= NN) return;
    int o0 = off[warp], o1 = off[warp + 1];
    float4 a = ((const float4*)(x + (size_t)warp * INF))[lane];
    int j = o0;
    for (; j + 3 < o1; j += 4) {
        float4 v0 = ((const float4*)(x + (size_t)col[j]     * INF))[lane];
        float4 v1 = ((const float4*)(x + (size_t)col[j + 1] * INF))[lane];
        float4 v2 = ((const float4*)(x + (size_t)col[j + 2] * INF))[lane];
        float4 v3 = ((const float4*)(x + (size_t)col[j + 3] * INF))[lane];
        a.x += (v0.x + v1.x) + (v2.x + v3.x);
        a.y += (v0.y + v1.y) + (v2.y + v3.y);
        a.z += (v0.z + v1.z) + (v2.z + v3.z);
        a.w += (v0.w + v1.w) + (v2.w + v3.w);
    }
    for (; j < o1; j++) {
        float4 v = ((const float4*)(x + (size_t)col[j] * INF))[lane];
        a.x += v.x; a.y += v.y; a.z += v.z; a.w += v.w;
    }
    uint32_t h0, l0, h1, l1;
    bfsplit2(a.x, a.y, h0, l0);
    bfsplit2(a.z, a.w, h1, l1);
    *(uint2*)&aggH[(size_t)warp * 64 + lane * 2] = make_uint2(h0, h1);
    *(uint2*)&aggL[(size_t)warp * 64 + lane * 2] = make_uint2(l0, l1);
}

// ===== layers 2/3 aggregation from split cat (hi+lo reconstruct) =============
// 4-neighbor unrolled (8 independent uint4 loads in flight).
// Block 0 also resets the BN stats accumulators (safe: runs after the GEMM2
// that consumed them, before the GEMM1 that refills them — stream order).
__global__ __launch_bounds__(256)
void csr_agg_sp(const uint32_t* __restrict__ H, const uint32_t* __restrict__ L,
                int woff,
                const int* __restrict__ off, const int* __restrict__ col,
                uint32_t* __restrict__ aggH, uint32_t* __restrict__ aggL,
                float* __restrict__ sum, float* __restrict__ sumsq)
{
    if (blockIdx.x == 0 && threadIdx.x < HH) {
        sum[threadIdx.x]   = 0.f;
        sumsq[threadIdx.x] = 0.f;
    }
    int warp = (blockIdx.x * blockDim.x + threadIdx.x) >> 5;
    int lane = threadIdx.x & 31;
    if (warp >= NN) return;
    int o0 = off[warp], o1 = off[warp + 1];

    float a[8];
    {
        size_t b = (size_t)warp * 384 + woff + lane * 4;
        uint4 hw = *(const uint4*)(H + b);
        uint4 lw = *(const uint4*)(L + b);
        float2 h, l;
        h = up2(hw.x); l = up2(lw.x); a[0] = h.x + l.x; a[1] = h.y + l.y;
        h = up2(hw.y); l = up2(lw.y); a[2] = h.x + l.x; a[3] = h.y + l.y;
        h = up2(hw.z); l = up2(lw.z); a[4] = h.x + l.x; a[5] = h.y + l.y;
        h = up2(hw.w); l = up2(lw.w); a[6] = h.x + l.x; a[7] = h.y + l.y;
    }
    int j = o0;
    for (; j + 3 < o1; j += 4) {
        size_t b0 = (size_t)col[j]     * 384 + woff + lane * 4;
        size_t b1 = (size_t)col[j + 1] * 384 + woff + lane * 4;
        size_t b2 = (size_t)col[j + 2] * 384 + woff + lane * 4;
        size_t b3 = (size_t)col[j + 3] * 384 + woff + lane * 4;
        uint4 hw0 = *(const uint4*)(H + b0);
        uint4 lw0 = *(const uint4*)(L + b0);
        uint4 hw1 = *(const uint4*)(H + b1);
        uint4 lw1 = *(const uint4*)(L + b1);
        uint4 hw2 = *(const uint4*)(H + b2);
        uint4 lw2 = *(const uint4*)(L + b2);
        uint4 hw3 = *(const uint4*)(H + b3);
        uint4 lw3 = *(const uint4*)(L + b3);
        float2 p0, q0, p1, q1, p2, q2, p3, q3;
#define ACC2(comp, i0, i1)                                                   \
        p0 = up2(hw0.comp); q0 = up2(lw0.comp);                              \
        p1 = up2(hw1.comp); q1 = up2(lw1.comp);                              \
        p2 = up2(hw2.comp); q2 = up2(lw2.comp);                              \
        p3 = up2(hw3.comp); q3 = up2(lw3.comp);                              \
        a[i0] += ((p0.x + q0.x) + (p1.x + q1.x)) +                           \
                 ((p2.x + q2.x) + (p3.x + q3.x));                            \
        a[i1] += ((p0.y + q0.y) + (p1.y + q1.y)) +                           \
                 ((p2.y + q2.y) + (p3.y + q3.y));
        ACC2(x, 0, 1)
        ACC2(y, 2, 3)
        ACC2(z, 4, 5)
        ACC2(w, 6, 7)
#undef ACC2
    }
    for (; j < o1; j++) {
        size_t b = (size_t)col[j] * 384 + woff + lane * 4;
        uint4 hw = *(const uint4*)(H + b);
        uint4 lw = *(const uint4*)(L + b);
        float2 h, l;
        h = up2(hw.x); l = up2(lw.x); a[0] += h.x + l.x; a[1] += h.y + l.y;
        h = up2(hw.y); l = up2(lw.y); a[2] += h.x + l.x; a[3] += h.y + l.y;
        h = up2(hw.z); l = up2(lw.z); a[4] += h.x + l.x; a[5] += h.y + l.y;
        h = up2(hw.w); l = up2(lw.w); a[6] += h.x + l.x; a[7] += h.y + l.y;
    }
    uint4 oh, ol;
    bfsplit2(a[0], a[1], oh.x, ol.x);
    bfsplit2(a[2], a[3], oh.y, ol.y);
    bfsplit2(a[4], a[5], oh.z, ol.z);
    bfsplit2(a[6], a[7], oh.w, ol.w);
    *(uint4*)&aggH[(size_t)warp * 128 + lane * 4] = oh;
    *(uint4*)&aggL[(size_t)warp * 128 + lane * 4] = ol;
}

// ================= bf16x3 mma.sync GEMM ======================================
__device__ __forceinline__ void mma16(float* c, const uint32_t* a, const uint32_t* b)
{
    asm volatile("mma.sync.aligned.m16n8k16.row.col.f32.bf16.bf16.f32 "
                 "{%0,%1,%2,%3}, {%4,%5,%6,%7}, {%8,%9}, {%0,%1,%2,%3};"
                 : "+f"(c[0]), "+f"(c[1]), "+f"(c[2]), "+f"(c[3])
                 : "r"(a[0]), "r"(a[1]), "r"(a[2]), "r"(a[3]),
                   "r"(b[0]), "r"(b[1]));
}

#define BM 128
#define BN 128
#define LDB_W 136

// KSTEP: k-words per pipeline stage (8 or 16).
// AMODE: 0 = split A via cp.async;
//        2 = fp32 A + fused BN(relu)+split (KSTEP must be 8); in this mode
//            `scale`/`shift` params carry gamma/beta and `sumv`/`sumsqv`
//            carry the completed BN stats — scale/shift computed per-CTA.
// MODE:  0 = fp32 C out; 1 = split Hi/Lo out; 2 = fused lin2 head (atomics)
// STATS: 1 = accumulate column sum/sumsq of (acc+bias) into sumv/sumsqv
template<int KSTEP, int AMODE, int RELU, int MODE, int STATS>
__global__ __launch_bounds__(256, 2)
void gemm_tc(const uint32_t* __restrict__ AH, const uint32_t* __restrict__ AL,
             const float* __restrict__ Afp, int ldaW,
             const uint32_t* __restrict__ BH, const uint32_t* __restrict__ BL,
             int Nc,
             const float* __restrict__ bias,
             const float* __restrict__ scale, const float* __restrict__ shift,
             float* __restrict__ C, int ldc,
             uint32_t* __restrict__ OH, uint32_t* __restrict__ OL,
             int ldoW, int colbase,
             const float* __restrict__ w2, float* __restrict__ outp,
             float* __restrict__ sumv, float* __restrict__ sumsqv,
             int M, int Kw)
{
    const int LDA_W = KSTEP + 4;
    __shared__ __align__(16) uint32_t AsH[2][BM * (KSTEP + 4)];
    __shared__ __align__(16) uint32_t AsL[2][BM * (KSTEP + 4)];
    __shared__ __align__(16) uint32_t BsH[2][KSTEP * LDB_W];
    __shared__ __align__(16) uint32_t BsL[2][KSTEP * LDB_W];
    __shared__ float s_scale[(AMODE == 2) ? HH : 1];
    __shared__ float s_shift[(AMODE == 2) ? HH : 1];

    const int tid  = threadIdx.x;
    const int lane = tid & 31;
    const int wid  = tid >> 5;
    const int gid  = lane >> 2, tig = lane & 3;
    const int wm = (wid & 1) * 64;
    const int wn = (wid >> 1) * 32;
    const int m0 = blockIdx.y * BM;
    const int n0 = blockIdx.x * BN;

    if (AMODE == 2) {
        // per-CTA BN finalize (identical fp ops to a standalone bnfin kernel)
        int c = tid;                    // blockDim == HH
        const float invN = 1.f / (float)NN;
        float mu  = sumv[c] * invN;
        float var = fmaxf(sumsqv[c] * invN - mu * mu, 0.f);
        float sc  = scale[c] * rsqrtf(var + 1e-5f);   // scale = gamma
        s_scale[c] = sc;
        s_shift[c] = shift[c] - mu * sc;              // shift = beta
        __syncthreads();
    }

    const int am = tid >> 1;
    const int aw = (tid & 1) * (KSTEP / 2);
    const int garow = min(m0 + am, M - 1);
    const uint32_t* ArowH = AH + (size_t)garow * ldaW + aw;
    const uint32_t* ArowL = AL + (size_t)garow * ldaW + aw;
    const float*    ArowF = Afp + (size_t)garow * (ldaW * 2) + aw * 2;
    const uint32_t* BrowH = BH + (size_t)wid * Nc + n0 + lane * 4;
    const uint32_t* BrowL = BL + (size_t)wid * Nc + n0 + lane * 4;

    uint32_t dAH[2], dAL[2], dBH[2], dBL[2];
#pragma unroll
    for (int s = 0; s < 2; s++) {
        dAH[s] = s2u(&AsH[s][am * LDA_W + aw]);
        dAL[s] = s2u(&AsL[s][am * LDA_W + aw]);
        dBH[s] = s2u(&BsH[s][wid * LDB_W + lane * 4]);
        dBL[s] = s2u(&BsL[s][wid * LDB_W + lane * 4]);
    }

    float acc[4][4][4];
#pragma unroll
    for (int i = 0; i < 4; i++)
#pragma unroll
        for (int j = 0; j < 4; j++)
#pragma unroll
            for (int k = 0; k < 4; k++) acc[i][j][k] = 0.f;

    float aR[8];

    auto issueB = [&](int k2, int s) {
        CP16(dBH[s], BrowH + (size_t)k2 * Nc);
        CP16(dBL[s], BrowL + (size_t)k2 * Nc);
        if (KSTEP == 16) {
            CP16(dBH[s] + 8 * LDB_W * 4, BrowH + (size_t)(k2 + 8) * Nc);
            CP16(dBL[s] + 8 * LDB_W * 4, BrowL + (size_t)(k2 + 8) * Nc);
        }
        CP_COMMIT();
    };
    auto issueA0 = [&](int k2, int s) {
        CP16(dAH[s], ArowH + k2);
        CP16(dAL[s], ArowL + k2);
        if (KSTEP == 16) {
            CP16(dAH[s] + 16, ArowH + k2 + 4);
            CP16(dAL[s] + 16, ArowL + k2 + 4);
        }
    };
    auto loadA2 = [&](int k2) {
        const float* p = ArowF + k2 * 2;
        float4 u0 = *(const float4*)(p);
        float4 u1 = *(const float4*)(p + 4);
        aR[0]=u0.x; aR[1]=u0.y; aR[2]=u0.z; aR[3]=u0.w;
        aR[4]=u1.x; aR[5]=u1.y; aR[6]=u1.z; aR[7]=u1.w;
    };
    auto stsA2 = [&](int k2, int s) {
        int ke = k2 * 2 + aw * 2;
        float v[8];
#pragma unroll
        for (int j = 0; j < 8; j++)
            v[j] = fmaxf(fmaf(aR[j], s_scale[ke + j], s_shift[ke + j]), 0.f);
        uint4 hv, lv;
        bfsplit2(v[0], v[1], hv.x, lv.x);
        bfsplit2(v[2], v[3], hv.y, lv.y);
        bfsplit2(v[4], v[5], hv.z, lv.z);
        bfsplit2(v[6], v[7], hv.w, lv.w);
        *(uint4*)&AsH[s][am * LDA_W + aw] = hv;
        *(uint4*)&AsL[s][am * LDA_W + aw] = lv;
    };

    auto compute = [&](int st) {
#pragma unroll
        for (int kb = 0; kb < KSTEP; kb += 8) {
            uint32_t bH[4][2], bL[4][2];
#pragma unroll
            for (int nt = 0; nt < 4; nt++) {
                int n = wn + nt * 8 + gid;
                bH[nt][0] = BsH[st][(kb + tig)     * LDB_W + n];
                bH[nt][1] = BsH[st][(kb + tig + 4) * LDB_W + n];
                bL[nt][0] = BsL[st][(kb + tig)     * LDB_W + n];
                bL[nt][1] = BsL[st][(kb + tig + 4) * LDB_W + n];
            }
#pragma unroll
            for (int mt = 0; mt < 4; mt++) {
                int r0 = (wm + mt * 16 + gid) * LDA_W + kb;
                int r8 = r0 + 8 * LDA_W;
                uint32_t aHr[4], aLr[4];
                aHr[0] = AsH[st][r0 + tig];
                aHr[1] = AsH[st][r8 + tig];
                aHr[2] = AsH[st][r0 + tig + 4];
                aHr[3] = AsH[st][r8 + tig + 4];
                aLr[0] = AsL[st][r0 + tig];
                aLr[1] = AsL[st][r8 + tig];
                aLr[2] = AsL[st][r0 + tig + 4];
                aLr[3] = AsL[st][r8 + tig + 4];
#pragma unroll
                for (int nt = 0; nt < 4; nt++) {
                    mma16(acc[mt][nt], aLr, bH[nt]);
                    mma16(acc[mt][nt], aHr, bL[nt]);
                    mma16(acc[mt][nt], aHr, bH[nt]);
                }
            }
        }
    };

    const int ntg = Kw / KSTEP;
    // prologue
    if (AMODE == 0) {
        issueA0(0, 0);
        issueB(0, 0);
    } else {
        loadA2(0);
        stsA2(0, 0);
        issueB(0, 0);
    }
    int st = 0;
    for (int t = 0; t < ntg; t++) {
        bool has = (t + 1) < ntg;
        if (AMODE == 2 && has) loadA2((t + 1) * KSTEP);
        CP_WAIT0();
        __syncthreads();
        if (has) {
            if (AMODE == 0) issueA0((t + 1) * KSTEP, st ^ 1);
            issueB((t + 1) * KSTEP, st ^ 1);
        }
        compute(st);
        if (AMODE == 2 && has) stsA2((t + 1) * KSTEP, st ^ 1);
        st ^= 1;
    }

    // ---------------- epilogue ----------------
    if (MODE == 2) {
        float l0a[8] = {0,0,0,0,0,0,0,0};
        float l1a[8] = {0,0,0,0,0,0,0,0};
#pragma unroll
        for (int ntl = 0; ntl < 4; ntl++) {
            int cn = n0 + wn + ntl * 8 + tig * 2;
            float b0 = bias[cn], b1 = bias[cn + 1];
            float w00 = w2[cn * 2],     w01 = w2[cn * 2 + 1];
            float w10 = w2[cn * 2 + 2], w11 = w2[cn * 2 + 3];
#pragma unroll
            for (int half = 0; half < 2; half++) {
#pragma unroll
                for (int mt = 0; mt < 4; mt++) {
                    const float* c = acc[mt][ntl];
                    float v0 = fmaxf(c[half * 2 + 0] + b0, 0.f);
                    float v1 = fmaxf(c[half * 2 + 1] + b1, 0.f);
                    int id = mt * 2 + half;
                    l0a[id] += v0 * w00 + v1 * w10;
                    l1a[id] += v0 * w01 + v1 * w11;
                }
            }
        }
#pragma unroll
        for (int half = 0; half < 2; half++) {
#pragma unroll
            for (int mt = 0; mt < 4; mt++) {
                int id = mt * 2 + half;
                float l0 = l0a[id], l1 = l1a[id];
                l0 += __shfl_xor_sync(0xffffffffu, l0, 1);
                l0 += __shfl_xor_sync(0xffffffffu, l0, 2);
                l1 += __shfl_xor_sync(0xffffffffu, l1, 1);
                l1 += __shfl_xor_sync(0xffffffffu, l1, 2);
                int r = m0 + wm + mt * 16 + gid + half * 8;
                if (tig == 0 && r < M) {
                    atomicAdd(&outp[r * 2],     l0);
                    atomicAdd(&outp[r * 2 + 1], l1);
                }
            }
        }
        return;
    }

#pragma unroll
    for (int ntl = 0; ntl < 4; ntl++) {
        int cn = n0 + wn + ntl * 8 + tig * 2;
        float b0 = bias[cn], b1 = bias[cn + 1];
        float s0 = 0.f, s1 = 0.f, q0 = 0.f, q1 = 0.f;
#pragma unroll
        for (int half = 0; half < 2; half++) {
#pragma unroll
            for (int mt = 0; mt < 4; mt++) {
                int r = m0 + wm + mt * 16 + gid + half * 8;
                if (r >= M) continue;
                const float* c = acc[mt][ntl];
                float v0 = c[half * 2 + 0] + b0;
                float v1 = c[half * 2 + 1] + b1;
                if (RELU) { v0 = fmaxf(v0, 0.f); v1 = fmaxf(v1, 0.f); }
                if (MODE == 0) {
                    *(float2*)&C[(size_t)r * ldc + cn] = make_float2(v0, v1);
                } else {
                    uint32_t hw, lw;
                    bfsplit2(v0, v1, hw, lw);
                    size_t wo = (size_t)r * ldoW + ((colbase + cn) >> 1);
                    OH[wo] = hw;
                    OL[wo] = lw;
                }
                if (STATS) {
                    s0 += v0; q0 += v0 * v0;
                    s1 += v1; q1 += v1 * v1;
                }
            }
        }
        if (STATS) {
#pragma unroll
            for (int o = 4; o < 32; o <<= 1) {
                s0 += __shfl_xor_sync(0xffffffffu, s0, o);
                s1 += __shfl_xor_sync(0xffffffffu, s1, o);
                q0 += __shfl_xor_sync(0xffffffffu, q0, o);
                q1 += __shfl_xor_sync(0xffffffffu, q1, o);
            }
            if (gid == 0) {
                atomicAdd(&sumv[cn],       s0);
                atomicAdd(&sumv[cn + 1],   s1);
                atomicAdd(&sumsqv[cn],     q0);
                atomicAdd(&sumsqv[cn + 1], q1);
            }
        }
    }
}

// ================= head init + softmax =======================================
// init_out_k also resets BN stats after layer 3 (runs post layer-3 GEMM2).
__global__ void init_out_k(float* __restrict__ out, const float* __restrict__ b,
                           float* __restrict__ sum, float* __restrict__ sumsq)
{
    int i = blockIdx.x * blockDim.x + threadIdx.x;
    if (i < NN * 2) out[i] = b[i & 1];
    if (i < HH) { sum[i] = 0.f; sumsq[i] = 0.f; }
}

__global__ void softmax_k(float* __restrict__ out, int half)
{
    int i = blockIdx.x * blockDim.x + threadIdx.x;
    if (i >= NN) return;
    float a0 = out[i * 2], a1 = out[i * 2 + 1];
    float m  = fmaxf(a0, a1);
    float e0 = expf(a0 - m);
    float e1 = expf(a1 - m);
    float inv = 1.f / (e0 + e1);
    out[half + i * 2]     = e0 * inv;
    out[half + i * 2 + 1] = e1 * inv;
}

// ================= host orchestration =======================================
struct Ptrs {
    float *h, *sum, *sumsq;
    uint32_t *aggH, *aggL, *catH, *catL, *WH, *WL;
    int *deg, *off, *cur, *col;
};

#define MT ((NN + 127) / 128)

static void run_layer(int layer, const Ptrs& P, int w1off, int w2off,
                      const float* xin,
                      const float* b1, const float* gg, const float* be,
                      const float* b2, int catcol)
{
    int aggBlocks = (NN + 7) / 8;
    if (layer == 1)
        csr_agg1<<<aggBlocks, 256>>>(xin, P.off, P.col, P.aggH, P.aggL);
    else
        csr_agg_sp<<<aggBlocks, 256>>>(P.catH, P.catL, (layer - 2) * 128,
                                       P.off, P.col, P.aggH, P.aggL,
                                       P.sum, P.sumsq);

    int Kw = (layer == 1) ? 64 : 128;
    dim3 g1(HH / BN, MT);
    // GEMM1 with fused BN stats (sum/sumsq arrive zeroed)
    gemm_tc<16, 0, 0, 0, 1><<<g1, 256>>>(P.aggH, P.aggL, nullptr, Kw,
                                         P.WH + w1off, P.WL + w1off, HH, b1,
                                         nullptr, nullptr,
                                         P.h, HH, nullptr, nullptr, 0, 0,
                                         nullptr, nullptr, P.sum, P.sumsq, NN, Kw);

    // GEMM2 with per-CTA BN finalize + fused transform/relu/split on A-load
    gemm_tc<8, 2, 1, 1, 0><<<g1, 256>>>(nullptr, nullptr, P.h, 128,
                                        P.WH + w2off, P.WL + w2off, HH, b2,
                                        gg, be,
                                        nullptr, 0, P.catH, P.catL, 384, catcol,
                                        nullptr, nullptr, P.sum, P.sumsq, NN, 128);
}

extern "C" void kernel_launch(void* const* d_in, const int* in_sizes, int n_in,
                              void* d_out, int out_size)
{
    const float* x  = (const float*)d_in[0];
    const int*   ei = (const int*)d_in[1];

    const float* c1_W1 = (const float*)d_in[2];
    const float* c1_b1 = (const float*)d_in[3];
    const float* c1_g  = (const float*)d_in[4];
    const float* c1_be = (const float*)d_in[5];
    const float* c1_W2 = (const float*)d_in[6];
    const float* c1_b2 = (const float*)d_in[7];

    const float* c2_W1 = (const float*)d_in[8];
    const float* c2_b1 = (const float*)d_in[9];
    const float* c2_g  = (const float*)d_in[10];
    const float* c2_be = (const float*)d_in[11];
    const float* c2_W2 = (const float*)d_in[12];
    const float* c2_b2 = (const float*)d_in[13];

    const float* c3_W1 = (const float*)d_in[14];
    const float* c3_b1 = (const float*)d_in[15];
    const float* c3_g  = (const float*)d_in[16];
    const float* c3_be = (const float*)d_in[17];
    const float* c3_W2 = (const float*)d_in[18];
    const float* c3_b2 = (const float*)d_in[19];

    const float* lin1_W = (const float*)d_in[20];
    const float* lin1_b = (const float*)d_in[21];
    const float* lin2_W = (const float*)d_in[22];
    const float* lin2_b = (const float*)d_in[23];

    Ptrs P;
    cudaGetSymbolAddress((void**)&P.h,     g_h);
    cudaGetSymbolAddress((void**)&P.sum,   g_sum);
    cudaGetSymbolAddress((void**)&P.sumsq, g_sumsq);
    cudaGetSymbolAddress((void**)&P.aggH,  g_aggH);
    cudaGetSymbolAddress((void**)&P.aggL,  g_aggL);
    cudaGetSymbolAddress((void**)&P.catH,  g_catH);
    cudaGetSymbolAddress((void**)&P.catL,  g_catL);
    cudaGetSymbolAddress((void**)&P.WH,    g_WH);
    cudaGetSymbolAddress((void**)&P.WL,    g_WL);
    cudaGetSymbolAddress((void**)&P.deg,   g_deg);
    cudaGetSymbolAddress((void**)&P.off,   g_off);
    cudaGetSymbolAddress((void**)&P.cur,   g_cur);
    cudaGetSymbolAddress((void**)&P.col,   g_col);

    prep_all<<<(W_TOT + 255) / 256, 256>>>(c1_W1, c1_W2, c2_W1, c2_W2,
                                           c3_W1, c3_W2, lin1_W, P.WH, P.WL);

    // deg arrives zeroed (module load / previous scan_k reset)
    hist_k<<<(EE + 255) / 256, 256>>>(ei, P.deg);
    scan_k<<<1, 1024>>>(P.deg, P.off, P.cur);
    fill_k<<<(EE + 255) / 256, 256>>>(ei, P.cur, P.col);

    run_layer(1, P, W_C1W1, W_C1W2, x, c1_b1, c1_g, c1_be, c1_b2, 0);
    run_layer(2, P, W_C2W1, W_C2W2, nullptr, c2_b1, c2_g, c2_be, c2_b2, HH);
    run_layer(3, P, W_C3W1, W_C3W2, nullptr, c3_b1, c3_g, c3_be, c3_b2, 2 * HH);

    // fused readout: lin1 (relu) + lin2 via atomics, then softmax
    float* out = (float*)d_out;
    init_out_k<<<(NN * 2 + 255) / 256, 256>>>(out, lin2_b, P.sum, P.sumsq);

    dim3 gridL(H3 / BN, MT);
    gemm_tc<16, 0, 1, 2, 0><<<gridL, 256>>>(P.catH, P.catL, nullptr, 384,
                                            P.WH + W_LIN1, P.WL + W_LIN1, H3, lin1_b,
                                            nullptr, nullptr,
                                            nullptr, 0, nullptr, nullptr, 0, 0,
                                            lin2_W, out, nullptr, nullptr, NN, 384);

    int half = out_size / 2;
    softmax_k<<<(NN + 255) / 256, 256>>>(out, half);
}

// round 17
// speedup vs baseline: 1.0042x; 1.0042x over previous
#include <cuda_runtime.h>
#include <cuda_bf16.h>
#include <cstdint>

#define NN   50000
#define EE   800000
#define INF  128
#define HH   256
#define H3   768

// ---------------- scratch (static device globals; no allocations) ----------
__device__ float    g_h    [(size_t)NN * HH];          // pre-BN hidden (fp32)
__device__ uint32_t g_aggH [(size_t)NN * 128];         // split (x+agg) packed k-pairs
__device__ uint32_t g_aggL [(size_t)NN * 128];
__device__ uint32_t g_catH [(size_t)NN * 384];         // split concat(h1,h2,h3)
__device__ uint32_t g_catL [(size_t)NN * 384];
__device__ uint32_t g_WH   [475136];                   // split weights [K/2][N]
__device__ uint32_t g_WL   [475136];
__device__ float    g_sum  [HH];                       // zero at load; reset by agg/init
__device__ float    g_sumsq[HH];
__device__ int      g_deg  [NN];                       // zero at load; scan_k re-zeroes
__device__ int      g_off  [NN + 1];
__device__ int      g_cur  [NN];
__device__ int      g_col  [EE];

#define W_C1W1 0
#define W_C1W2 16384
#define W_C2W1 49152
#define W_C2W2 81920
#define W_C3W1 114688
#define W_C3W2 147456
#define W_LIN1 180224
#define W_TOT  475136

// ---------------- bf16 split helpers ----------------------------------------
__device__ __forceinline__ uint32_t pk2(__nv_bfloat16 lo, __nv_bfloat16 hi)
{
    __nv_bfloat162 t; t.x = lo; t.y = hi;
    return *reinterpret_cast<uint32_t*>(&t);
}
__device__ __forceinline__ void bfsplit2(float v0, float v1,
                                         uint32_t& hw, uint32_t& lw)
{
    __nv_bfloat16 h0 = __float2bfloat16(v0);
    __nv_bfloat16 h1 = __float2bfloat16(v1);
    float l0 = v0 - __bfloat162float(h0);
    float l1 = v1 - __bfloat162float(h1);
    hw = pk2(h0, h1);
    lw = pk2(__float2bfloat16(l0), __float2bfloat16(l1));
}
__device__ __forceinline__ float2 up2(uint32_t w)
{
    __nv_bfloat162 t = *reinterpret_cast<__nv_bfloat162*>(&w);
    return make_float2(__bfloat162float(t.x), __bfloat162float(t.y));
}

// ---------------- cp.async helpers -------------------------------------------
#define CP16(dst, src) \
    asm volatile("cp.async.ca.shared.global [%0], [%1], 16;" :: "r"(dst), "l"(src) : "memory")
#define CP_COMMIT() asm volatile("cp.async.commit_group;" ::: "memory")
#define CP_WAIT0()  asm volatile("cp.async.wait_group 0;"  ::: "memory")

__device__ __forceinline__ uint32_t s2u(const void* p)
{
    return (uint32_t)__cvta_generic_to_shared(p);
}

// ================= consolidated weight pre-split =============================
__global__ void prep_all(const float* __restrict__ w0, const float* __restrict__ w1,
                         const float* __restrict__ w2, const float* __restrict__ w3,
                         const float* __restrict__ w4, const float* __restrict__ w5,
                         const float* __restrict__ w6,
                         uint32_t* __restrict__ H, uint32_t* __restrict__ L)
{
    int idx = blockIdx.x * blockDim.x + threadIdx.x;
    if (idx >= W_TOT) return;
    const float* src;
    int base, n;
    if      (idx < W_C1W2) { src = w0; base = W_C1W1; n = HH; }
    else if (idx < W_C2W1) { src = w1; base = W_C1W2; n = HH; }
    else if (idx < W_C2W2) { src = w2; base = W_C2W1; n = HH; }
    else if (idx < W_C3W1) { src = w3; base = W_C2W2; n = HH; }
    else if (idx < W_C3W2) { src = w4; base = W_C3W1; n = HH; }
    else if (idx < W_LIN1) { src = w5; base = W_C3W2; n = HH; }
    else                   { src = w6; base = W_LIN1; n = H3; }
    int loc = idx - base;
    int k2 = loc / n, nn = loc - k2 * n;
    float v0 = src[(size_t)(2 * k2)     * n + nn];
    float v1 = src[(size_t)(2 * k2 + 1) * n + nn];
    bfsplit2(v0, v1, H[idx], L[idx]);
}

// ================= CSR build =================================================
__global__ void hist_k(const int* __restrict__ ei, int* __restrict__ deg)
{
    int e = blockIdx.x * blockDim.x + threadIdx.x;
    if (e < EE) atomicAdd(&deg[ei[EE + e]], 1);
}

// scan + self-reset of deg (keeps launch-invariant: deg == 0 on entry)
__global__ void scan_k(int* __restrict__ deg, int* __restrict__ off,
                       int* __restrict__ cur)
{
    __shared__ int wsum[32];
    __shared__ int carry;
    int tid = threadIdx.x, lane = tid & 31, w = tid >> 5;
    if (tid == 0) { carry = 0; off[0] = 0; }
    __syncthreads();
    for (int base = 0; base < NN; base += 1024) {
        int i = base + tid;
        int v = 0;
        if (i < NN) { v = deg[i]; deg[i] = 0; }
        int s = v;
#pragma unroll
        for (int o = 1; o < 32; o <<= 1) {
            int t = __shfl_up_sync(0xffffffffu, s, o);
            if (lane >= o) s += t;
        }
        if (lane == 31) wsum[w] = s;
        __syncthreads();
        if (w == 0) {
            int ws = wsum[lane];
#pragma unroll
            for (int o = 1; o < 32; o <<= 1) {
                int t = __shfl_up_sync(0xffffffffu, ws, o);
                if (lane >= o) ws += t;
            }
            wsum[lane] = ws;
        }
        __syncthreads();
        int inc = s + (w > 0 ? wsum[w - 1] : 0) + carry;
        if (i < NN) { off[i + 1] = inc; cur[i] = inc - v; }
        int tot = wsum[31];
        __syncthreads();
        if (tid == 0) carry += tot;
        __syncthreads();
    }
}

__global__ void fill_k(const int* __restrict__ ei, int* __restrict__ cur,
                       int* __restrict__ col)
{
    int e = blockIdx.x * blockDim.x + threadIdx.x;
    if (e < EE) {
        int p = atomicAdd(&cur[ei[EE + e]], 1);
        col[p] = ei[e];
    }
}

// ===== layer-1 aggregation from fp32 x: split(x + sum_neighbors x) ==========
// 4-neighbor unrolled (4 independent float4 streams in flight; low reg cost).
__global__ __launch_bounds__(256)
void csr_agg1(const float* __restrict__ x,
              const int* __restrict__ off, const int* __restrict__ col,
              uint32_t* __restrict__ aggH, uint32_t* __restrict__ aggL)
{
    int warp = (blockIdx.x * blockDim.x + threadIdx.x) >> 5;
    int lane = threadIdx.x & 31;
    if (warp >= NN) return;
    int o0 = off[warp], o1 = off[warp + 1];
    float4 a = ((const float4*)(x + (size_t)warp * INF))[lane];
    int j = o0;
    for (; j + 3 < o1; j += 4) {
        float4 v0 = ((const float4*)(x + (size_t)col[j]     * INF))[lane];
        float4 v1 = ((const float4*)(x + (size_t)col[j + 1] * INF))[lane];
        float4 v2 = ((const float4*)(x + (size_t)col[j + 2] * INF))[lane];
        float4 v3 = ((const float4*)(x + (size_t)col[j + 3] * INF))[lane];
        a.x += (v0.x + v1.x) + (v2.x + v3.x);
        a.y += (v0.y + v1.y) + (v2.y + v3.y);
        a.z += (v0.z + v1.z) + (v2.z + v3.z);
        a.w += (v0.w + v1.w) + (v2.w + v3.w);
    }
    for (; j < o1; j++) {
        float4 v = ((const float4*)(x + (size_t)col[j] * INF))[lane];
        a.x += v.x; a.y += v.y; a.z += v.z; a.w += v.w;
    }
    uint32_t h0, l0, h1, l1;
    bfsplit2(a.x, a.y, h0, l0);
    bfsplit2(a.z, a.w, h1, l1);
    *(uint2*)&aggH[(size_t)warp * 64 + lane * 2] = make_uint2(h0, h1);
    *(uint2*)&aggL[(size_t)warp * 64 + lane * 2] = make_uint2(l0, l1);
}

// ===== layers 2/3 aggregation from split cat (hi+lo reconstruct) =============
// 2-neighbor unrolled (4 independent uint4 loads; measured best — 4-wide
// regressed from register pressure, round 16).
// Block 0 also resets the BN stats accumulators (safe: runs after the GEMM2
// that consumed them, before the GEMM1 that refills them — stream order).
__global__ __launch_bounds__(256)
void csr_agg_sp(const uint32_t* __restrict__ H, const uint32_t* __restrict__ L,
                int woff,
                const int* __restrict__ off, const int* __restrict__ col,
                uint32_t* __restrict__ aggH, uint32_t* __restrict__ aggL,
                float* __restrict__ sum, float* __restrict__ sumsq)
{
    if (blockIdx.x == 0 && threadIdx.x < HH) {
        sum[threadIdx.x]   = 0.f;
        sumsq[threadIdx.x] = 0.f;
    }
    int warp = (blockIdx.x * blockDim.x + threadIdx.x) >> 5;
    int lane = threadIdx.x & 31;
    if (warp >= NN) return;
    int o0 = off[warp], o1 = off[warp + 1];

    float a[8];
    {
        size_t b = (size_t)warp * 384 + woff + lane * 4;
        uint4 hw = *(const uint4*)(H + b);
        uint4 lw = *(const uint4*)(L + b);
        float2 h, l;
        h = up2(hw.x); l = up2(lw.x); a[0] = h.x + l.x; a[1] = h.y + l.y;
        h = up2(hw.y); l = up2(lw.y); a[2] = h.x + l.x; a[3] = h.y + l.y;
        h = up2(hw.z); l = up2(lw.z); a[4] = h.x + l.x; a[5] = h.y + l.y;
        h = up2(hw.w); l = up2(lw.w); a[6] = h.x + l.x; a[7] = h.y + l.y;
    }
    int j = o0;
    for (; j + 1 < o1; j += 2) {
        size_t b0 = (size_t)col[j]     * 384 + woff + lane * 4;
        size_t b1 = (size_t)col[j + 1] * 384 + woff + lane * 4;
        uint4 hw0 = *(const uint4*)(H + b0);
        uint4 lw0 = *(const uint4*)(L + b0);
        uint4 hw1 = *(const uint4*)(H + b1);
        uint4 lw1 = *(const uint4*)(L + b1);
        float2 h0, l0, h1, l1;
        h0 = up2(hw0.x); l0 = up2(lw0.x); h1 = up2(hw1.x); l1 = up2(lw1.x);
        a[0] += (h0.x + l0.x) + (h1.x + l1.x);
        a[1] += (h0.y + l0.y) + (h1.y + l1.y);
        h0 = up2(hw0.y); l0 = up2(lw0.y); h1 = up2(hw1.y); l1 = up2(lw1.y);
        a[2] += (h0.x + l0.x) + (h1.x + l1.x);
        a[3] += (h0.y + l0.y) + (h1.y + l1.y);
        h0 = up2(hw0.z); l0 = up2(lw0.z); h1 = up2(hw1.z); l1 = up2(lw1.z);
        a[4] += (h0.x + l0.x) + (h1.x + l1.x);
        a[5] += (h0.y + l0.y) + (h1.y + l1.y);
        h0 = up2(hw0.w); l0 = up2(lw0.w); h1 = up2(hw1.w); l1 = up2(lw1.w);
        a[6] += (h0.x + l0.x) + (h1.x + l1.x);
        a[7] += (h0.y + l0.y) + (h1.y + l1.y);
    }
    if (j < o1) {
        size_t b = (size_t)col[j] * 384 + woff + lane * 4;
        uint4 hw = *(const uint4*)(H + b);
        uint4 lw = *(const uint4*)(L + b);
        float2 h, l;
        h = up2(hw.x); l = up2(lw.x); a[0] += h.x + l.x; a[1] += h.y + l.y;
        h = up2(hw.y); l = up2(lw.y); a[2] += h.x + l.x; a[3] += h.y + l.y;
        h = up2(hw.z); l = up2(lw.z); a[4] += h.x + l.x; a[5] += h.y + l.y;
        h = up2(hw.w); l = up2(lw.w); a[6] += h.x + l.x; a[7] += h.y + l.y;
    }
    uint4 oh, ol;
    bfsplit2(a[0], a[1], oh.x, ol.x);
    bfsplit2(a[2], a[3], oh.y, ol.y);
    bfsplit2(a[4], a[5], oh.z, ol.z);
    bfsplit2(a[6], a[7], oh.w, ol.w);
    *(uint4*)&aggH[(size_t)warp * 128 + lane * 4] = oh;
    *(uint4*)&aggL[(size_t)warp * 128 + lane * 4] = ol;
}

// ================= bf16x3 mma.sync GEMM ======================================
__device__ __forceinline__ void mma16(float* c, const uint32_t* a, const uint32_t* b)
{
    asm volatile("mma.sync.aligned.m16n8k16.row.col.f32.bf16.bf16.f32 "
                 "{%0,%1,%2,%3}, {%4,%5,%6,%7}, {%8,%9}, {%0,%1,%2,%3};"
                 : "+f"(c[0]), "+f"(c[1]), "+f"(c[2]), "+f"(c[3])
                 : "r"(a[0]), "r"(a[1]), "r"(a[2]), "r"(a[3]),
                   "r"(b[0]), "r"(b[1]));
}

#define BM 128
#define BN 128
#define LDB_W 136

// KSTEP: k-words per pipeline stage (8 or 16).
// AMODE: 0 = split A via cp.async;
//        2 = fp32 A + fused BN(relu)+split (KSTEP must be 8); in this mode
//            `scale`/`shift` params carry gamma/beta and `sumv`/`sumsqv`
//            carry the completed BN stats — scale/shift computed per-CTA.
// MODE:  0 = fp32 C out; 1 = split Hi/Lo out; 2 = fused lin2 head (atomics)
// STATS: 1 = accumulate column sum/sumsq of (acc+bias) into sumv/sumsqv
template<int KSTEP, int AMODE, int RELU, int MODE, int STATS>
__global__ __launch_bounds__(256, 2)
void gemm_tc(const uint32_t* __restrict__ AH, const uint32_t* __restrict__ AL,
             const float* __restrict__ Afp, int ldaW,
             const uint32_t* __restrict__ BH, const uint32_t* __restrict__ BL,
             int Nc,
             const float* __restrict__ bias,
             const float* __restrict__ scale, const float* __restrict__ shift,
             float* __restrict__ C, int ldc,
             uint32_t* __restrict__ OH, uint32_t* __restrict__ OL,
             int ldoW, int colbase,
             const float* __restrict__ w2, float* __restrict__ outp,
             float* __restrict__ sumv, float* __restrict__ sumsqv,
             int M, int Kw)
{
    const int LDA_W = KSTEP + 4;
    __shared__ __align__(16) uint32_t AsH[2][BM * (KSTEP + 4)];
    __shared__ __align__(16) uint32_t AsL[2][BM * (KSTEP + 4)];
    __shared__ __align__(16) uint32_t BsH[2][KSTEP * LDB_W];
    __shared__ __align__(16) uint32_t BsL[2][KSTEP * LDB_W];
    __shared__ float s_scale[(AMODE == 2) ? HH : 1];
    __shared__ float s_shift[(AMODE == 2) ? HH : 1];

    const int tid  = threadIdx.x;
    const int lane = tid & 31;
    const int wid  = tid >> 5;
    const int gid  = lane >> 2, tig = lane & 3;
    const int wm = (wid & 1) * 64;
    const int wn = (wid >> 1) * 32;
    const int m0 = blockIdx.y * BM;
    const int n0 = blockIdx.x * BN;

    if (AMODE == 2) {
        // per-CTA BN finalize (identical fp ops to a standalone bnfin kernel)
        int c = tid;                    // blockDim == HH
        const float invN = 1.f / (float)NN;
        float mu  = sumv[c] * invN;
        float var = fmaxf(sumsqv[c] * invN - mu * mu, 0.f);
        float sc  = scale[c] * rsqrtf(var + 1e-5f);   // scale = gamma
        s_scale[c] = sc;
        s_shift[c] = shift[c] - mu * sc;              // shift = beta
        __syncthreads();
    }

    const int am = tid >> 1;
    const int aw = (tid & 1) * (KSTEP / 2);
    const int garow = min(m0 + am, M - 1);
    const uint32_t* ArowH = AH + (size_t)garow * ldaW + aw;
    const uint32_t* ArowL = AL + (size_t)garow * ldaW + aw;
    const float*    ArowF = Afp + (size_t)garow * (ldaW * 2) + aw * 2;
    const uint32_t* BrowH = BH + (size_t)wid * Nc + n0 + lane * 4;
    const uint32_t* BrowL = BL + (size_t)wid * Nc + n0 + lane * 4;

    uint32_t dAH[2], dAL[2], dBH[2], dBL[2];
#pragma unroll
    for (int s = 0; s < 2; s++) {
        dAH[s] = s2u(&AsH[s][am * LDA_W + aw]);
        dAL[s] = s2u(&AsL[s][am * LDA_W + aw]);
        dBH[s] = s2u(&BsH[s][wid * LDB_W + lane * 4]);
        dBL[s] = s2u(&BsL[s][wid * LDB_W + lane * 4]);
    }

    float acc[4][4][4];
#pragma unroll
    for (int i = 0; i < 4; i++)
#pragma unroll
        for (int j = 0; j < 4; j++)
#pragma unroll
            for (int k = 0; k < 4; k++) acc[i][j][k] = 0.f;

    float aR[8];

    auto issueB = [&](int k2, int s) {
        CP16(dBH[s], BrowH + (size_t)k2 * Nc);
        CP16(dBL[s], BrowL + (size_t)k2 * Nc);
        if (KSTEP == 16) {
            CP16(dBH[s] + 8 * LDB_W * 4, BrowH + (size_t)(k2 + 8) * Nc);
            CP16(dBL[s] + 8 * LDB_W * 4, BrowL + (size_t)(k2 + 8) * Nc);
        }
        CP_COMMIT();
    };
    auto issueA0 = [&](int k2, int s) {
        CP16(dAH[s], ArowH + k2);
        CP16(dAL[s], ArowL + k2);
        if (KSTEP == 16) {
            CP16(dAH[s] + 16, ArowH + k2 + 4);
            CP16(dAL[s] + 16, ArowL + k2 + 4);
        }
    };
    auto loadA2 = [&](int k2) {
        const float* p = ArowF + k2 * 2;
        float4 u0 = *(const float4*)(p);
        float4 u1 = *(const float4*)(p + 4);
        aR[0]=u0.x; aR[1]=u0.y; aR[2]=u0.z; aR[3]=u0.w;
        aR[4]=u1.x; aR[5]=u1.y; aR[6]=u1.z; aR[7]=u1.w;
    };
    auto stsA2 = [&](int k2, int s) {
        int ke = k2 * 2 + aw * 2;
        float v[8];
#pragma unroll
        for (int j = 0; j < 8; j++)
            v[j] = fmaxf(fmaf(aR[j], s_scale[ke + j], s_shift[ke + j]), 0.f);
        uint4 hv, lv;
        bfsplit2(v[0], v[1], hv.x, lv.x);
        bfsplit2(v[2], v[3], hv.y, lv.y);
        bfsplit2(v[4], v[5], hv.z, lv.z);
        bfsplit2(v[6], v[7], hv.w, lv.w);
        *(uint4*)&AsH[s][am * LDA_W + aw] = hv;
        *(uint4*)&AsL[s][am * LDA_W + aw] = lv;
    };

    auto compute = [&](int st) {
#pragma unroll
        for (int kb = 0; kb < KSTEP; kb += 8) {
            uint32_t bH[4][2], bL[4][2];
#pragma unroll
            for (int nt = 0; nt < 4; nt++) {
                int n = wn + nt * 8 + gid;
                bH[nt][0] = BsH[st][(kb + tig)     * LDB_W + n];
                bH[nt][1] = BsH[st][(kb + tig + 4) * LDB_W + n];
                bL[nt][0] = BsL[st][(kb + tig)     * LDB_W + n];
                bL[nt][1] = BsL[st][(kb + tig + 4) * LDB_W + n];
            }
#pragma unroll
            for (int mt = 0; mt < 4; mt++) {
                int r0 = (wm + mt * 16 + gid) * LDA_W + kb;
                int r8 = r0 + 8 * LDA_W;
                uint32_t aHr[4], aLr[4];
                aHr[0] = AsH[st][r0 + tig];
                aHr[1] = AsH[st][r8 + tig];
                aHr[2] = AsH[st][r0 + tig + 4];
                aHr[3] = AsH[st][r8 + tig + 4];
                aLr[0] = AsL[st][r0 + tig];
                aLr[1] = AsL[st][r8 + tig];
                aLr[2] = AsL[st][r0 + tig + 4];
                aLr[3] = AsL[st][r8 + tig + 4];
#pragma unroll
                for (int nt = 0; nt < 4; nt++) {
                    mma16(acc[mt][nt], aLr, bH[nt]);
                    mma16(acc[mt][nt], aHr, bL[nt]);
                    mma16(acc[mt][nt], aHr, bH[nt]);
                }
            }
        }
    };

    const int ntg = Kw / KSTEP;
    // prologue
    if (AMODE == 0) {
        issueA0(0, 0);
        issueB(0, 0);
    } else {
        loadA2(0);
        stsA2(0, 0);
        issueB(0, 0);
    }
    int st = 0;
    for (int t = 0; t < ntg; t++) {
        bool has = (t + 1) < ntg;
        if (AMODE == 2 && has) loadA2((t + 1) * KSTEP);
        CP_WAIT0();
        __syncthreads();
        if (has) {
            if (AMODE == 0) issueA0((t + 1) * KSTEP, st ^ 1);
            issueB((t + 1) * KSTEP, st ^ 1);
        }
        compute(st);
        if (AMODE == 2 && has) stsA2((t + 1) * KSTEP, st ^ 1);
        st ^= 1;
    }

    // ---------------- epilogue ----------------
    if (MODE == 2) {
        float l0a[8] = {0,0,0,0,0,0,0,0};
        float l1a[8] = {0,0,0,0,0,0,0,0};
#pragma unroll
        for (int ntl = 0; ntl < 4; ntl++) {
            int cn = n0 + wn + ntl * 8 + tig * 2;
            float b0 = bias[cn], b1 = bias[cn + 1];
            float w00 = w2[cn * 2],     w01 = w2[cn * 2 + 1];
            float w10 = w2[cn * 2 + 2], w11 = w2[cn * 2 + 3];
#pragma unroll
            for (int half = 0; half < 2; half++) {
#pragma unroll
                for (int mt = 0; mt < 4; mt++) {
                    const float* c = acc[mt][ntl];
                    float v0 = fmaxf(c[half * 2 + 0] + b0, 0.f);
                    float v1 = fmaxf(c[half * 2 + 1] + b1, 0.f);
                    int id = mt * 2 + half;
                    l0a[id] += v0 * w00 + v1 * w10;
                    l1a[id] += v0 * w01 + v1 * w11;
                }
            }
        }
#pragma unroll
        for (int half = 0; half < 2; half++) {
#pragma unroll
            for (int mt = 0; mt < 4; mt++) {
                int id = mt * 2 + half;
                float l0 = l0a[id], l1 = l1a[id];
                l0 += __shfl_xor_sync(0xffffffffu, l0, 1);
                l0 += __shfl_xor_sync(0xffffffffu, l0, 2);
                l1 += __shfl_xor_sync(0xffffffffu, l1, 1);
                l1 += __shfl_xor_sync(0xffffffffu, l1, 2);
                int r = m0 + wm + mt * 16 + gid + half * 8;
                if (tig == 0 && r < M) {
                    atomicAdd(&outp[r * 2],     l0);
                    atomicAdd(&outp[r * 2 + 1], l1);
                }
            }
        }
        return;
    }

#pragma unroll
    for (int ntl = 0; ntl < 4; ntl++) {
        int cn = n0 + wn + ntl * 8 + tig * 2;
        float b0 = bias[cn], b1 = bias[cn + 1];
        float s0 = 0.f, s1 = 0.f, q0 = 0.f, q1 = 0.f;
#pragma unroll
        for (int half = 0; half < 2; half++) {
#pragma unroll
            for (int mt = 0; mt < 4; mt++) {
                int r = m0 + wm + mt * 16 + gid + half * 8;
                if (r >= M) continue;
                const float* c = acc[mt][ntl];
                float v0 = c[half * 2 + 0] + b0;
                float v1 = c[half * 2 + 1] + b1;
                if (RELU) { v0 = fmaxf(v0, 0.f); v1 = fmaxf(v1, 0.f); }
                if (MODE == 0) {
                    *(float2*)&C[(size_t)r * ldc + cn] = make_float2(v0, v1);
                } else {
                    uint32_t hw, lw;
                    bfsplit2(v0, v1, hw, lw);
                    size_t wo = (size_t)r * ldoW + ((colbase + cn) >> 1);
                    OH[wo] = hw;
                    OL[wo] = lw;
                }
                if (STATS) {
                    s0 += v0; q0 += v0 * v0;
                    s1 += v1; q1 += v1 * v1;
                }
            }
        }
        if (STATS) {
#pragma unroll
            for (int o = 4; o < 32; o <<= 1) {
                s0 += __shfl_xor_sync(0xffffffffu, s0, o);
                s1 += __shfl_xor_sync(0xffffffffu, s1, o);
                q0 += __shfl_xor_sync(0xffffffffu, q0, o);
                q1 += __shfl_xor_sync(0xffffffffu, q1, o);
            }
            if (gid == 0) {
                atomicAdd(&sumv[cn],       s0);
                atomicAdd(&sumv[cn + 1],   s1);
                atomicAdd(&sumsqv[cn],     q0);
                atomicAdd(&sumsqv[cn + 1], q1);
            }
        }
    }
}

// ================= head init + softmax =======================================
// init_out_k also resets BN stats after layer 3 (runs post layer-3 GEMM2).
__global__ void init_out_k(float* __restrict__ out, const float* __restrict__ b,
                           float* __restrict__ sum, float* __restrict__ sumsq)
{
    int i = blockIdx.x * blockDim.x + threadIdx.x;
    if (i < NN * 2) out[i] = b[i & 1];
    if (i < HH) { sum[i] = 0.f; sumsq[i] = 0.f; }
}

__global__ void softmax_k(float* __restrict__ out, int half)
{
    int i = blockIdx.x * blockDim.x + threadIdx.x;
    if (i >= NN) return;
    float a0 = out[i * 2], a1 = out[i * 2 + 1];
    float m  = fmaxf(a0, a1);
    float e0 = expf(a0 - m);
    float e1 = expf(a1 - m);
    float inv = 1.f / (e0 + e1);
    out[half + i * 2]     = e0 * inv;
    out[half + i * 2 + 1] = e1 * inv;
}

// ================= host orchestration =======================================
struct Ptrs {
    float *h, *sum, *sumsq;
    uint32_t *aggH, *aggL, *catH, *catL, *WH, *WL;
    int *deg, *off, *cur, *col;
};

#define MT ((NN + 127) / 128)

static void run_layer(int layer, const Ptrs& P, int w1off, int w2off,
                      const float* xin,
                      const float* b1, const float* gg, const float* be,
                      const float* b2, int catcol)
{
    int aggBlocks = (NN + 7) / 8;
    if (layer == 1)
        csr_agg1<<<aggBlocks, 256>>>(xin, P.off, P.col, P.aggH, P.aggL);
    else
        csr_agg_sp<<<aggBlocks, 256>>>(P.catH, P.catL, (layer - 2) * 128,
                                       P.off, P.col, P.aggH, P.aggL,
                                       P.sum, P.sumsq);

    int Kw = (layer == 1) ? 64 : 128;
    dim3 g1(HH / BN, MT);
    // GEMM1 with fused BN stats (sum/sumsq arrive zeroed)
    gemm_tc<16, 0, 0, 0, 1><<<g1, 256>>>(P.aggH, P.aggL, nullptr, Kw,
                                         P.WH + w1off, P.WL + w1off, HH, b1,
                                         nullptr, nullptr,
                                         P.h, HH, nullptr, nullptr, 0, 0,
                                         nullptr, nullptr, P.sum, P.sumsq, NN, Kw);

    // GEMM2 with per-CTA BN finalize + fused transform/relu/split on A-load
    gemm_tc<8, 2, 1, 1, 0><<<g1, 256>>>(nullptr, nullptr, P.h, 128,
                                        P.WH + w2off, P.WL + w2off, HH, b2,
                                        gg, be,
                                        nullptr, 0, P.catH, P.catL, 384, catcol,
                                        nullptr, nullptr, P.sum, P.sumsq, NN, 128);
}

extern "C" void kernel_launch(void* const* d_in, const int* in_sizes, int n_in,
                              void* d_out, int out_size)
{
    const float* x  = (const float*)d_in[0];
    const int*   ei = (const int*)d_in[1];

    const float* c1_W1 = (const float*)d_in[2];
    const float* c1_b1 = (const float*)d_in[3];
    const float* c1_g  = (const float*)d_in[4];
    const float* c1_be = (const float*)d_in[5];
    const float* c1_W2 = (const float*)d_in[6];
    const float* c1_b2 = (const float*)d_in[7];

    const float* c2_W1 = (const float*)d_in[8];
    const float* c2_b1 = (const float*)d_in[9];
    const float* c2_g  = (const float*)d_in[10];
    const float* c2_be = (const float*)d_in[11];
    const float* c2_W2 = (const float*)d_in[12];
    const float* c2_b2 = (const float*)d_in[13];

    const float* c3_W1 = (const float*)d_in[14];
    const float* c3_b1 = (const float*)d_in[15];
    const float* c3_g  = (const float*)d_in[16];
    const float* c3_be = (const float*)d_in[17];
    const float* c3_W2 = (const float*)d_in[18];
    const float* c3_b2 = (const float*)d_in[19];

    const float* lin1_W = (const float*)d_in[20];
    const float* lin1_b = (const float*)d_in[21];
    const float* lin2_W = (const float*)d_in[22];
    const float* lin2_b = (const float*)d_in[23];

    Ptrs P;
    cudaGetSymbolAddress((void**)&P.h,     g_h);
    cudaGetSymbolAddress((void**)&P.sum,   g_sum);
    cudaGetSymbolAddress((void**)&P.sumsq, g_sumsq);
    cudaGetSymbolAddress((void**)&P.aggH,  g_aggH);
    cudaGetSymbolAddress((void**)&P.aggL,  g_aggL);
    cudaGetSymbolAddress((void**)&P.catH,  g_catH);
    cudaGetSymbolAddress((void**)&P.catL,  g_catL);
    cudaGetSymbolAddress((void**)&P.WH,    g_WH);
    cudaGetSymbolAddress((void**)&P.WL,    g_WL);
    cudaGetSymbolAddress((void**)&P.deg,   g_deg);
    cudaGetSymbolAddress((void**)&P.off,   g_off);
    cudaGetSymbolAddress((void**)&P.cur,   g_cur);
    cudaGetSymbolAddress((void**)&P.col,   g_col);

    prep_all<<<(W_TOT + 255) / 256, 256>>>(c1_W1, c1_W2, c2_W1, c2_W2,
                                           c3_W1, c3_W2, lin1_W, P.WH, P.WL);

    // deg arrives zeroed (module load / previous scan_k reset)
    hist_k<<<(EE + 255) / 256, 256>>>(ei, P.deg);
    scan_k<<<1, 1024>>>(P.deg, P.off, P.cur);
    fill_k<<<(EE + 255) / 256, 256>>>(ei, P.cur, P.col);

    run_layer(1, P, W_C1W1, W_C1W2, x, c1_b1, c1_g, c1_be, c1_b2, 0);
    run_layer(2, P, W_C2W1, W_C2W2, nullptr, c2_b1, c2_g, c2_be, c2_b2, HH);
    run_layer(3, P, W_C3W1, W_C3W2, nullptr, c3_b1, c3_g, c3_be, c3_b2, 2 * HH);

    // fused readout: lin1 (relu) + lin2 via atomics, then softmax
    float* out = (float*)d_out;
    init_out_k<<<(NN * 2 + 255) / 256, 256>>>(out, lin2_b, P.sum, P.sumsq);

    dim3 gridL(H3 / BN, MT);
    gemm_tc<16, 0, 1, 2, 0><<<gridL, 256>>>(P.catH, P.catL, nullptr, 384,
                                            P.WH + W_LIN1, P.WL + W_LIN1, H3, lin1_b,
                                            nullptr, nullptr,
                                            nullptr, 0, nullptr, nullptr, 0, 0,
                                            lin2_W, out, nullptr, nullptr, NN, 384);

    int half = out_size / 2;
    softmax_k<<<(NN + 255) / 256, 256>>>(out, half);
}